// round 10
// baseline (speedup 1.0000x reference)
#include <cuda_runtime.h>
#include <cuda_bf16.h>
#include <math.h>
#include <stdint.h>

#define B_ 4
#define T_ 2048
#define C_ 1024
#define H_ 16
#define D_ 64
#define M_ (B_*T_)    // 8192
#define N3_ (3*C_)    // 3072
#define BH_ (B_*H_)   // 64

// ---------------------------------------------------------------------------
// Scratch (__device__ globals: allocation-free rule)
// ---------------------------------------------------------------------------
__device__ __nv_bfloat16 g_Xhi[(size_t)M_*C_];
__device__ __nv_bfloat16 g_Xlo[(size_t)M_*C_];
__device__ __nv_bfloat16 g_A2hi[(size_t)M_*C_];
__device__ __nv_bfloat16 g_A2lo[(size_t)M_*C_];
__device__ __nv_bfloat16 g_WqkvT_hi[(size_t)N3_*C_];
__device__ __nv_bfloat16 g_WqkvT_lo[(size_t)N3_*C_];
__device__ __nv_bfloat16 g_WprojT_hi[(size_t)C_*C_];
__device__ __nv_bfloat16 g_WprojT_lo[(size_t)C_*C_];

__device__ __nv_bfloat16 g_Qhi[(size_t)BH_*T_*D_];   // [bh][t][d], pre-scaled D^-0.5
__device__ __nv_bfloat16 g_Qlo[(size_t)BH_*T_*D_];
__device__ __nv_bfloat16 g_Khi[(size_t)BH_*T_*D_];
__device__ __nv_bfloat16 g_Klo[(size_t)BH_*T_*D_];
__device__ __nv_bfloat16 g_Vthi[(size_t)BH_*D_*T_];  // [bh][d][t] (transposed)
__device__ __nv_bfloat16 g_Vtlo[(size_t)BH_*D_*T_];

// ---------------------------------------------------------------------------
// PTX helpers (portable sm_80+ path: compiles for vanilla sm_103)
// ---------------------------------------------------------------------------
__device__ __forceinline__ uint32_t smem_to_u32(const void* p) {
    uint32_t a;
    asm("{ .reg .u64 t; cvta.to.shared.u64 t, %1; cvt.u32.u64 %0, t; }"
        : "=r"(a) : "l"(p));
    return a;
}
__device__ __forceinline__ void ldsm4(uint32_t* r, uint32_t addr) {
    asm volatile("ldmatrix.sync.aligned.m8n8.x4.shared.b16 {%0,%1,%2,%3}, [%4];"
                 : "=r"(r[0]), "=r"(r[1]), "=r"(r[2]), "=r"(r[3]) : "r"(addr));
}
__device__ __forceinline__ void mma16816(float* c, const uint32_t* a,
                                         uint32_t b0, uint32_t b1) {
    asm volatile(
        "mma.sync.aligned.m16n8k16.row.col.f32.bf16.bf16.f32 "
        "{%0,%1,%2,%3}, {%4,%5,%6,%7}, {%8,%9}, {%0,%1,%2,%3};"
        : "+f"(c[0]), "+f"(c[1]), "+f"(c[2]), "+f"(c[3])
        : "r"(a[0]), "r"(a[1]), "r"(a[2]), "r"(a[3]), "r"(b0), "r"(b1));
}
__device__ __forceinline__ void cpa16(uint32_t s, const void* g) {
    asm volatile("cp.async.cg.shared.global [%0], [%1], 16;" :: "r"(s), "l"(g));
}
#define CP_COMMIT() asm volatile("cp.async.commit_group;" ::: "memory")
#define CP_WAIT1()  asm volatile("cp.async.wait_group 1;" ::: "memory")

// Swizzled smem tile: [rows][128B rows], 16B chunks XOR-swizzled (8-row period)
__device__ __forceinline__ uint32_t lda_sw(int r, int c) {
    return (uint32_t)((r << 7) | (((c ^ (r & 7)) & 7) << 4));
}
__device__ __forceinline__ uint32_t pack_bf16(float lo_, float hi_) {
    __nv_bfloat162 t = __floats2bfloat162_rn(lo_, hi_);
    return *(uint32_t*)&t;
}
__device__ __forceinline__ void store_hl2(__nv_bfloat16* Hp, __nv_bfloat16* Lp,
                                          size_t off, float v0, float v1) {
    __nv_bfloat16 h0 = __float2bfloat16_rn(v0);
    __nv_bfloat16 h1 = __float2bfloat16_rn(v1);
    __nv_bfloat16 l0 = __float2bfloat16_rn(v0 - __bfloat162float(h0));
    __nv_bfloat16 l1 = __float2bfloat16_rn(v1 - __bfloat162float(h1));
    *(__nv_bfloat162*)(Hp + off) = __nv_bfloat162(h0, h1);
    *(__nv_bfloat162*)(Lp + off) = __nv_bfloat162(l0, l1);
}

// ---------------------------------------------------------------------------
// Conversion kernels (raw inputs only)
// ---------------------------------------------------------------------------
__global__ void conv_x(const float* __restrict__ in) {
    size_t i = (size_t)blockIdx.x * blockDim.x + threadIdx.x;
    float4 v = ((const float4*)in)[i];
    float f[4] = {v.x, v.y, v.z, v.w};
    __nv_bfloat16 h[4], l[4];
#pragma unroll
    for (int k = 0; k < 4; k++) {
        h[k] = __float2bfloat16_rn(f[k]);
        l[k] = __float2bfloat16_rn(f[k] - __bfloat162float(h[k]));
    }
    ((__nv_bfloat162*)(g_Xhi + i * 4))[0] = __nv_bfloat162(h[0], h[1]);
    ((__nv_bfloat162*)(g_Xhi + i * 4))[1] = __nv_bfloat162(h[2], h[3]);
    ((__nv_bfloat162*)(g_Xlo + i * 4))[0] = __nv_bfloat162(l[0], l[1]);
    ((__nv_bfloat162*)(g_Xlo + i * 4))[1] = __nv_bfloat162(l[2], l[3]);
}

template<int WHICH>   // 0: w_qkv -> g_WqkvT_*, 1: w_proj -> g_WprojT_*
__global__ void transpose_split(const float* __restrict__ W, int Kdim, int Ndim) {
    __nv_bfloat16* Thi = WHICH ? g_WprojT_hi : g_WqkvT_hi;
    __nv_bfloat16* Tlo = WHICH ? g_WprojT_lo : g_WqkvT_lo;
    __shared__ float tile[32][33];
    int x = blockIdx.x * 32 + threadIdx.x;
    int y0 = blockIdx.y * 32;
#pragma unroll
    for (int j = 0; j < 32; j += 8)
        tile[threadIdx.y + j][threadIdx.x] = W[(size_t)(y0 + threadIdx.y + j) * Ndim + x];
    __syncthreads();
    int xo = y0 + threadIdx.x;
    int yo0 = blockIdx.x * 32;
#pragma unroll
    for (int j = 0; j < 32; j += 8) {
        float v = tile[threadIdx.x][threadIdx.y + j];
        __nv_bfloat16 h = __float2bfloat16_rn(v);
        __nv_bfloat16 l = __float2bfloat16_rn(v - __bfloat162float(h));
        size_t o = (size_t)(yo0 + threadIdx.y + j) * Kdim + xo;
        Thi[o] = h; Tlo[o] = l;
    }
}

// ---------------------------------------------------------------------------
// HMMA GEMM, cp.async 2-stage pipeline, 2 CTAs/SM. 128x128 CTA tile, 8 warps
// (64x32 warp tile), k-chunk 32. Smem rows interleave [32 hi | 32 lo] bf16 in
// one 128B row (chunks 0-3 = hi, 4-7 = lo) -> stage is A(16KB)+B(16KB)=32KB.
// acc += Ahi*Bhi + Ahi*Blo + Alo*Bhi.
// ---------------------------------------------------------------------------
#define GEMM_STG_BYTES 32768
#define GEMM_SMEM (2*GEMM_STG_BYTES)    // 65536 -> 2 CTAs/SM

__device__ __forceinline__ void gemm_prefetch(
    uint32_t sbase, const __nv_bfloat16* Ah, const __nv_bfloat16* Al,
    const __nv_bfloat16* Bh, const __nv_bfloat16* Bl,
    int m0, int n0, int k0, int tid) {
#pragma unroll
    for (int i = 0; i < 4; i++) {
        const int id = i * 256 + tid;          // 1024 chunk slots
        const int r = id >> 3, ch = id & 7;
        const uint32_t so = lda_sw(r, ch);
        const int kk = k0 + (ch & 3) * 8;      // hi: ch 0-3, lo: ch 4-7
        const size_t ga = (size_t)(m0 + r) * C_ + kk;
        const size_t gb = (size_t)(n0 + r) * C_ + kk;
        cpa16(sbase + so,         (ch < 4 ? Ah : Al) + ga);
        cpa16(sbase + 16384 + so, (ch < 4 ? Bh : Bl) + gb);
    }
}

template<int CFG>
__global__ __launch_bounds__(256, 2) void gemm_mma(const float* __restrict__ bias,
                                                   float* __restrict__ out) {
    extern __shared__ __align__(128) char gsm[];
    const __nv_bfloat16* Ah = CFG ? g_A2hi : g_Xhi;
    const __nv_bfloat16* Al = CFG ? g_A2lo : g_Xlo;
    const __nv_bfloat16* Bh = CFG ? g_WprojT_hi : g_WqkvT_hi;
    const __nv_bfloat16* Bl = CFG ? g_WprojT_lo : g_WqkvT_lo;

    const uint32_t sb = smem_to_u32(gsm);
    const int tid = threadIdx.x, lane = tid & 31, w = tid >> 5;
    const int wr = w >> 2, wc = w & 3;
    const int n0 = blockIdx.x * 128, m0 = blockIdx.y * 128;
    const int fr = lane & 15, fc = lane >> 4;

    float acc[4][4][4];
#pragma unroll
    for (int a = 0; a < 4; a++)
#pragma unroll
        for (int b = 0; b < 4; b++)
#pragma unroll
            for (int c = 0; c < 4; c++) acc[a][b][c] = 0.f;

    gemm_prefetch(sb, Ah, Al, Bh, Bl, m0, n0, 0, tid);
    CP_COMMIT();

    const int NCHUNK = C_ / 32;   // 32
    for (int c32 = 0; c32 < NCHUNK; c32++) {
        if (c32 + 1 < NCHUNK)
            gemm_prefetch(sb + ((c32 + 1) & 1) * GEMM_STG_BYTES,
                          Ah, Al, Bh, Bl, m0, n0, (c32 + 1) * 32, tid);
        CP_COMMIT();
        CP_WAIT1();
        __syncthreads();

        const uint32_t sA = sb + (c32 & 1) * GEMM_STG_BYTES;
        const uint32_t sB = sA + 16384;
#pragma unroll
        for (int ks = 0; ks < 2; ks++) {
            uint32_t a_h[4][4], a_l[4][4];
#pragma unroll
            for (int mt = 0; mt < 4; mt++) {
                const int ar = wr * 64 + mt * 16 + fr;
                ldsm4(a_h[mt], sA + lda_sw(ar, 2 * ks + fc));
                ldsm4(a_l[mt], sA + lda_sw(ar, 4 + 2 * ks + fc));
            }
#pragma unroll
            for (int nt2 = 0; nt2 < 2; nt2++) {
                uint32_t b_h[4], b_l[4];
                const int br = wc * 32 + nt2 * 16 + fr;
                ldsm4(b_h, sB + lda_sw(br, 2 * ks + fc));
                ldsm4(b_l, sB + lda_sw(br, 4 + 2 * ks + fc));
#pragma unroll
                for (int mt = 0; mt < 4; mt++) {
                    mma16816(acc[mt][nt2 * 2],     a_h[mt], b_h[0], b_h[2]);
                    mma16816(acc[mt][nt2 * 2 + 1], a_h[mt], b_h[1], b_h[3]);
                    mma16816(acc[mt][nt2 * 2],     a_h[mt], b_l[0], b_l[2]);
                    mma16816(acc[mt][nt2 * 2 + 1], a_h[mt], b_l[1], b_l[3]);
                    mma16816(acc[mt][nt2 * 2],     a_l[mt], b_h[0], b_h[2]);
                    mma16816(acc[mt][nt2 * 2 + 1], a_l[mt], b_h[1], b_h[3]);
                }
            }
        }
        __syncthreads();
    }

    // Epilogue
    const int grp = lane >> 2, qc = (lane & 3) * 2;
    const int which = n0 >> 10;      // CFG 0: 0=Q, 1=K, 2=V
#pragma unroll
    for (int mt = 0; mt < 4; mt++) {
        const int m1 = m0 + wr * 64 + mt * 16 + grp;
        const int m2 = m1 + 8;
        const int b1 = m1 >> 11, t1 = m1 & (T_ - 1);
        const int b2 = m2 >> 11, t2 = m2 & (T_ - 1);
#pragma unroll
        for (int nt = 0; nt < 4; nt++) {
            const int n = n0 + wc * 32 + nt * 8 + qc;
            const float bs0 = bias[n], bs1 = bias[n + 1];
            float v0 = acc[mt][nt][0] + bs0, v1 = acc[mt][nt][1] + bs1;
            float v2 = acc[mt][nt][2] + bs0, v3 = acc[mt][nt][3] + bs1;
            if (CFG == 1) {
                *(float2*)(out + (size_t)m1 * C_ + n) = make_float2(v0, v1);
                *(float2*)(out + (size_t)m2 * C_ + n) = make_float2(v2, v3);
            } else {
                const int ci = n & (C_ - 1);
                const int h = ci >> 6, d = ci & 63;
                if (which == 0) { v0 *= 0.125f; v1 *= 0.125f; v2 *= 0.125f; v3 *= 0.125f; }
                if (which < 2) {
                    __nv_bfloat16* Dh = which ? g_Khi : g_Qhi;
                    __nv_bfloat16* Dl = which ? g_Klo : g_Qlo;
                    store_hl2(Dh, Dl, (((size_t)(b1 * H_ + h)) * T_ + t1) * D_ + d, v0, v1);
                    store_hl2(Dh, Dl, (((size_t)(b2 * H_ + h)) * T_ + t2) * D_ + d, v2, v3);
                } else {
                    const size_t oA = (((size_t)(b1 * H_ + h)) * D_ + d) * T_ + t1;
                    const size_t oB = (((size_t)(b2 * H_ + h)) * D_ + d) * T_ + t2;
                    __nv_bfloat16 h0 = __float2bfloat16_rn(v0);
                    __nv_bfloat16 h1 = __float2bfloat16_rn(v1);
                    __nv_bfloat16 h2 = __float2bfloat16_rn(v2);
                    __nv_bfloat16 h3 = __float2bfloat16_rn(v3);
                    g_Vthi[oA] = h0;      g_Vtlo[oA] = __float2bfloat16_rn(v0 - __bfloat162float(h0));
                    g_Vthi[oA + T_] = h1; g_Vtlo[oA + T_] = __float2bfloat16_rn(v1 - __bfloat162float(h1));
                    g_Vthi[oB] = h2;      g_Vtlo[oB] = __float2bfloat16_rn(v2 - __bfloat162float(h2));
                    g_Vthi[oB + T_] = h3; g_Vtlo[oB + T_] = __float2bfloat16_rn(v3 - __bfloat162float(h3));
                }
            }
        }
    }
}

// ---------------------------------------------------------------------------
// HMMA flash attention, causal, cp.async 2-stage K/V pipeline. Br=Bc=64,
// D=64, 4 warps, 2 CTAs/SM. Heavy q-tiles scheduled first (reversed index).
// ---------------------------------------------------------------------------
#define FL_Q_BYTES 16384                 // Qhi, Qlo [64][64]bf16
#define FL_STG_BYTES 32768               // Khi,Klo,Vthi,Vtlo per stage
#define FL_SMEM (FL_Q_BYTES + 2*FL_STG_BYTES)   // 81920

__device__ __forceinline__ void fl_prefetch(uint32_t sbase, size_t bhk,
                                            size_t bhv, int kv0, int tid) {
#pragma unroll
    for (int i = 0; i < 4; i++) {
        const int id = i * 128 + tid;
        const int r = id >> 3, ch = id & 7;
        const uint32_t so = lda_sw(r, ch);
        const size_t gk = bhk + (size_t)(kv0 + r) * D_ + ch * 8;
        const size_t gv = bhv + (size_t)r * T_ + kv0 + ch * 8;
        cpa16(sbase + so,         g_Khi + gk);
        cpa16(sbase + 8192 + so,  g_Klo + gk);
        cpa16(sbase + 16384 + so, g_Vthi + gv);
        cpa16(sbase + 24576 + so, g_Vtlo + gv);
    }
}

__global__ __launch_bounds__(128) void flash_mma() {
    extern __shared__ __align__(128) char fsm[];
    const uint32_t sb = smem_to_u32(fsm);
    const uint32_t sQh = sb, sQl = sb + 8192;
    const int tid = threadIdx.x, lane = tid & 31, w = tid >> 5;
    const int bh = blockIdx.y, b = bh >> 4, h = bh & 15;
    const int qtile = gridDim.x - 1 - blockIdx.x;   // heavy tiles first
    const int qt0 = qtile * 64;
    const int fr = lane & 15, fc = lane >> 4;
    const int grp = lane >> 2, qc = (lane & 3) * 2;
    const int ntiles = qtile + 1;

    const size_t bhk = (size_t)bh * T_ * D_;
    const size_t bhv = (size_t)bh * D_ * T_;

    fl_prefetch(sb + FL_Q_BYTES, bhk, bhv, 0, tid);
    CP_COMMIT();
#pragma unroll
    for (int i = 0; i < 4; i++) {
        const int id = i * 128 + tid;
        const int r = id >> 3, ch = id & 7;
        const uint32_t so = lda_sw(r, ch);
        const size_t g = bhk + (size_t)(qt0 + r) * D_ + ch * 8;
        *(uint4*)(fsm + so)        = *(const uint4*)(g_Qhi + g);
        *(uint4*)(fsm + 8192 + so) = *(const uint4*)(g_Qlo + g);
    }
    __syncthreads();

    uint32_t qh[4][4], ql[4][4];
#pragma unroll
    for (int ks = 0; ks < 4; ks++) {
        const uint32_t off = lda_sw(w * 16 + fr, 2 * ks + fc);
        ldsm4(qh[ks], sQh + off);
        ldsm4(ql[ks], sQl + off);
    }

    float o[8][4];
#pragma unroll
    for (int d = 0; d < 8; d++)
#pragma unroll
        for (int r = 0; r < 4; r++) o[d][r] = 0.f;
    float mA = -1e30f, mB = -1e30f, lA = 0.f, lB = 0.f;

    const int rowA = qt0 + w * 16 + grp;
    const int rowB = rowA + 8;

    for (int it = 0; it < ntiles; it++) {
        if (it + 1 < ntiles)
            fl_prefetch(sb + FL_Q_BYTES + ((it + 1) & 1) * FL_STG_BYTES,
                        bhk, bhv, (it + 1) * 64, tid);
        CP_COMMIT();
        CP_WAIT1();
        __syncthreads();

        const uint32_t sKh = sb + FL_Q_BYTES + (it & 1) * FL_STG_BYTES;
        const uint32_t sKl = sKh + 8192, sVh = sKh + 16384, sVl = sKh + 24576;
        const int kv0 = it * 64;

        float s[8][4];
#pragma unroll
        for (int nt = 0; nt < 8; nt++)
#pragma unroll
            for (int r = 0; r < 4; r++) s[nt][r] = 0.f;

#pragma unroll
        for (int ks = 0; ks < 4; ks++) {
#pragma unroll
            for (int nt2 = 0; nt2 < 4; nt2++) {
                uint32_t bhr[4], blr[4];
                const uint32_t off = lda_sw(nt2 * 16 + fr, 2 * ks + fc);
                ldsm4(bhr, sKh + off);
                ldsm4(blr, sKl + off);
                mma16816(s[nt2 * 2],     qh[ks], bhr[0], bhr[2]);
                mma16816(s[nt2 * 2 + 1], qh[ks], bhr[1], bhr[3]);
                mma16816(s[nt2 * 2],     qh[ks], blr[0], blr[2]);
                mma16816(s[nt2 * 2 + 1], qh[ks], blr[1], blr[3]);
                mma16816(s[nt2 * 2],     ql[ks], bhr[0], bhr[2]);
                mma16816(s[nt2 * 2 + 1], ql[ks], bhr[1], bhr[3]);
            }
        }

        if (kv0 == qt0) {
#pragma unroll
            for (int nt = 0; nt < 8; nt++) {
                const int cb = kv0 + nt * 8 + qc;
                if (cb > rowA)     s[nt][0] = -1e30f;
                if (cb + 1 > rowA) s[nt][1] = -1e30f;
                if (cb > rowB)     s[nt][2] = -1e30f;
                if (cb + 1 > rowB) s[nt][3] = -1e30f;
            }
        }

        float mxA = -1e30f, mxB = -1e30f;
#pragma unroll
        for (int nt = 0; nt < 8; nt++) {
            mxA = fmaxf(mxA, fmaxf(s[nt][0], s[nt][1]));
            mxB = fmaxf(mxB, fmaxf(s[nt][2], s[nt][3]));
        }
        mxA = fmaxf(mxA, __shfl_xor_sync(0xffffffffu, mxA, 1));
        mxA = fmaxf(mxA, __shfl_xor_sync(0xffffffffu, mxA, 2));
        mxB = fmaxf(mxB, __shfl_xor_sync(0xffffffffu, mxB, 1));
        mxB = fmaxf(mxB, __shfl_xor_sync(0xffffffffu, mxB, 2));
        const float nmA = fmaxf(mA, mxA), nmB = fmaxf(mB, mxB);
        const float aA = __expf(mA - nmA), aB = __expf(mB - nmB);

        float p[8][4];
        float sumA = 0.f, sumB = 0.f;
#pragma unroll
        for (int nt = 0; nt < 8; nt++) {
            p[nt][0] = __expf(s[nt][0] - nmA);
            p[nt][1] = __expf(s[nt][1] - nmA);
            p[nt][2] = __expf(s[nt][2] - nmB);
            p[nt][3] = __expf(s[nt][3] - nmB);
            sumA += p[nt][0] + p[nt][1];
            sumB += p[nt][2] + p[nt][3];
        }
        sumA += __shfl_xor_sync(0xffffffffu, sumA, 1);
        sumA += __shfl_xor_sync(0xffffffffu, sumA, 2);
        sumB += __shfl_xor_sync(0xffffffffu, sumB, 1);
        sumB += __shfl_xor_sync(0xffffffffu, sumB, 2);
        lA = lA * aA + sumA;
        lB = lB * aB + sumB;
        mA = nmA; mB = nmB;
#pragma unroll
        for (int d = 0; d < 8; d++) {
            o[d][0] *= aA; o[d][1] *= aA;
            o[d][2] *= aB; o[d][3] *= aB;
        }

#pragma unroll
        for (int ks = 0; ks < 4; ks++) {
            float f0 = p[2 * ks][0], f1 = p[2 * ks][1];
            float f2 = p[2 * ks][2], f3 = p[2 * ks][3];
            float f4 = p[2 * ks + 1][0], f5 = p[2 * ks + 1][1];
            float f6 = p[2 * ks + 1][2], f7 = p[2 * ks + 1][3];
            float h0 = __bfloat162float(__float2bfloat16_rn(f0));
            float h1 = __bfloat162float(__float2bfloat16_rn(f1));
            float h2 = __bfloat162float(__float2bfloat16_rn(f2));
            float h3 = __bfloat162float(__float2bfloat16_rn(f3));
            float h4 = __bfloat162float(__float2bfloat16_rn(f4));
            float h5 = __bfloat162float(__float2bfloat16_rn(f5));
            float h6 = __bfloat162float(__float2bfloat16_rn(f6));
            float h7 = __bfloat162float(__float2bfloat16_rn(f7));
            uint32_t pa_h[4], pa_l[4];
            pa_h[0] = pack_bf16(h0, h1); pa_h[1] = pack_bf16(h2, h3);
            pa_h[2] = pack_bf16(h4, h5); pa_h[3] = pack_bf16(h6, h7);
            pa_l[0] = pack_bf16(f0 - h0, f1 - h1);
            pa_l[1] = pack_bf16(f2 - h2, f3 - h3);
            pa_l[2] = pack_bf16(f4 - h4, f5 - h5);
            pa_l[3] = pack_bf16(f6 - h6, f7 - h7);
#pragma unroll
            for (int dt2 = 0; dt2 < 4; dt2++) {
                uint32_t vh4[4], vl4[4];
                const uint32_t off = lda_sw(dt2 * 16 + fr, 2 * ks + fc);
                ldsm4(vh4, sVh + off);
                ldsm4(vl4, sVl + off);
                mma16816(o[dt2 * 2],     pa_h, vh4[0], vh4[2]);
                mma16816(o[dt2 * 2 + 1], pa_h, vh4[1], vh4[3]);
                mma16816(o[dt2 * 2],     pa_h, vl4[0], vl4[2]);
                mma16816(o[dt2 * 2 + 1], pa_h, vl4[1], vl4[3]);
                mma16816(o[dt2 * 2],     pa_l, vh4[0], vh4[2]);
                mma16816(o[dt2 * 2 + 1], pa_l, vh4[1], vh4[3]);
            }
        }
        __syncthreads();
    }

    const float invA = 1.0f / lA, invB = 1.0f / lB;
    const size_t baseA = ((size_t)(b * T_ + rowA)) * C_ + h * D_;
    const size_t baseB = ((size_t)(b * T_ + rowB)) * C_ + h * D_;
#pragma unroll
    for (int dt = 0; dt < 8; dt++) {
        const int d = dt * 8 + qc;
        store_hl2(g_A2hi, g_A2lo, baseA + d, o[dt][0] * invA, o[dt][1] * invA);
        store_hl2(g_A2hi, g_A2lo, baseB + d, o[dt][2] * invB, o[dt][3] * invB);
    }
}

// ---------------------------------------------------------------------------
extern "C" void kernel_launch(void* const* d_in, const int* in_sizes, int n_in,
                              void* d_out, int out_size) {
    const float* x      = (const float*)d_in[0];
    const float* w_qkv  = (const float*)d_in[1];
    const float* b_qkv  = (const float*)d_in[2];
    const float* w_proj = (const float*)d_in[3];
    const float* b_proj = (const float*)d_in[4];
    float* out = (float*)d_out;

    cudaFuncSetAttribute(gemm_mma<0>, cudaFuncAttributeMaxDynamicSharedMemorySize, GEMM_SMEM);
    cudaFuncSetAttribute(gemm_mma<1>, cudaFuncAttributeMaxDynamicSharedMemorySize, GEMM_SMEM);
    cudaFuncSetAttribute(flash_mma,   cudaFuncAttributeMaxDynamicSharedMemorySize, FL_SMEM);

    // 0) input conversions
    conv_x<<<(M_ * C_ / 4) / 256, 256>>>(x);
    transpose_split<0><<<dim3(N3_ / 32, C_ / 32), dim3(32, 8)>>>(w_qkv, C_, N3_);
    transpose_split<1><<<dim3(C_ / 32, C_ / 32), dim3(32, 8)>>>(w_proj, C_, C_);

    // 1) QKV GEMM (pipelined HMMA, 2 CTA/SM) -> fused bf16 Q/K/Vt epilogue
    gemm_mma<0><<<dim3(N3_ / 128, M_ / 128), 256, GEMM_SMEM>>>(b_qkv, nullptr);

    // 2) Causal flash attention (pipelined HMMA) -> g_A2 hi/lo
    flash_mma<<<dim3(T_ / 64, BH_), 128, FL_SMEM>>>();

    // 3) Output projection (pipelined HMMA, 2 CTA/SM) -> fp32 out
    gemm_mma<1><<<dim3(C_ / 128, M_ / 128), 256, GEMM_SMEM>>>(b_proj, out);
}

// round 16
// speedup vs baseline: 1.0285x; 1.0285x over previous
#include <cuda_runtime.h>
#include <cuda_bf16.h>
#include <math.h>
#include <stdint.h>

#define B_ 4
#define T_ 2048
#define C_ 1024
#define H_ 16
#define D_ 64
#define M_ (B_*T_)    // 8192
#define N3_ (3*C_)    // 3072
#define BH_ (B_*H_)   // 64

// ---------------------------------------------------------------------------
// Scratch (__device__ globals: allocation-free rule)
// ---------------------------------------------------------------------------
__device__ __nv_bfloat16 g_Xhi[(size_t)M_*C_];
__device__ __nv_bfloat16 g_Xlo[(size_t)M_*C_];
__device__ __nv_bfloat16 g_A2hi[(size_t)M_*C_];
__device__ __nv_bfloat16 g_A2lo[(size_t)M_*C_];
__device__ __nv_bfloat16 g_WqkvT_hi[(size_t)N3_*C_];
__device__ __nv_bfloat16 g_WqkvT_lo[(size_t)N3_*C_];
__device__ __nv_bfloat16 g_WprojT_hi[(size_t)C_*C_];
__device__ __nv_bfloat16 g_WprojT_lo[(size_t)C_*C_];

__device__ __nv_bfloat16 g_Qhi[(size_t)BH_*T_*D_];   // [bh][t][d], pre-scaled D^-0.5
__device__ __nv_bfloat16 g_Qlo[(size_t)BH_*T_*D_];
__device__ __nv_bfloat16 g_Khi[(size_t)BH_*T_*D_];
__device__ __nv_bfloat16 g_Klo[(size_t)BH_*T_*D_];
__device__ __nv_bfloat16 g_Vthi[(size_t)BH_*D_*T_];  // [bh][d][t] (transposed)
__device__ __nv_bfloat16 g_Vtlo[(size_t)BH_*D_*T_];

// ---------------------------------------------------------------------------
// PTX helpers (portable sm_80+ path: compiles for vanilla sm_103)
// ---------------------------------------------------------------------------
__device__ __forceinline__ uint32_t smem_to_u32(const void* p) {
    uint32_t a;
    asm("{ .reg .u64 t; cvta.to.shared.u64 t, %1; cvt.u32.u64 %0, t; }"
        : "=r"(a) : "l"(p));
    return a;
}
__device__ __forceinline__ void ldsm4(uint32_t* r, uint32_t addr) {
    asm volatile("ldmatrix.sync.aligned.m8n8.x4.shared.b16 {%0,%1,%2,%3}, [%4];"
                 : "=r"(r[0]), "=r"(r[1]), "=r"(r[2]), "=r"(r[3]) : "r"(addr));
}
__device__ __forceinline__ void mma16816(float* c, const uint32_t* a,
                                         uint32_t b0, uint32_t b1) {
    asm volatile(
        "mma.sync.aligned.m16n8k16.row.col.f32.bf16.bf16.f32 "
        "{%0,%1,%2,%3}, {%4,%5,%6,%7}, {%8,%9}, {%0,%1,%2,%3};"
        : "+f"(c[0]), "+f"(c[1]), "+f"(c[2]), "+f"(c[3])
        : "r"(a[0]), "r"(a[1]), "r"(a[2]), "r"(a[3]), "r"(b0), "r"(b1));
}
__device__ __forceinline__ void cpa16(uint32_t s, const void* g) {
    asm volatile("cp.async.cg.shared.global [%0], [%1], 16;" :: "r"(s), "l"(g));
}
#define CP_COMMIT() asm volatile("cp.async.commit_group;" ::: "memory")
#define CP_WAIT1()  asm volatile("cp.async.wait_group 1;" ::: "memory")

// Swizzled smem tile: [rows][128B rows], 16B chunks XOR-swizzled (8-row period)
__device__ __forceinline__ uint32_t lda_sw(int r, int c) {
    return (uint32_t)((r << 7) | (((c ^ (r & 7)) & 7) << 4));
}
__device__ __forceinline__ uint32_t pack_bf16(float lo_, float hi_) {
    __nv_bfloat162 t = __floats2bfloat162_rn(lo_, hi_);
    return *(uint32_t*)&t;
}
__device__ __forceinline__ void store_hl2(__nv_bfloat16* Hp, __nv_bfloat16* Lp,
                                          size_t off, float v0, float v1) {
    __nv_bfloat16 h0 = __float2bfloat16_rn(v0);
    __nv_bfloat16 h1 = __float2bfloat16_rn(v1);
    __nv_bfloat16 l0 = __float2bfloat16_rn(v0 - __bfloat162float(h0));
    __nv_bfloat16 l1 = __float2bfloat16_rn(v1 - __bfloat162float(h1));
    *(__nv_bfloat162*)(Hp + off) = __nv_bfloat162(h0, h1);
    *(__nv_bfloat162*)(Lp + off) = __nv_bfloat162(l0, l1);
}

// ---------------------------------------------------------------------------
// Conversion kernels (raw inputs only)
// ---------------------------------------------------------------------------
__global__ void conv_x(const float* __restrict__ in) {
    size_t i = (size_t)blockIdx.x * blockDim.x + threadIdx.x;
    float4 v = ((const float4*)in)[i];
    float f[4] = {v.x, v.y, v.z, v.w};
    __nv_bfloat16 h[4], l[4];
#pragma unroll
    for (int k = 0; k < 4; k++) {
        h[k] = __float2bfloat16_rn(f[k]);
        l[k] = __float2bfloat16_rn(f[k] - __bfloat162float(h[k]));
    }
    ((__nv_bfloat162*)(g_Xhi + i * 4))[0] = __nv_bfloat162(h[0], h[1]);
    ((__nv_bfloat162*)(g_Xhi + i * 4))[1] = __nv_bfloat162(h[2], h[3]);
    ((__nv_bfloat162*)(g_Xlo + i * 4))[0] = __nv_bfloat162(l[0], l[1]);
    ((__nv_bfloat162*)(g_Xlo + i * 4))[1] = __nv_bfloat162(l[2], l[3]);
}

template<int WHICH>   // 0: w_qkv -> g_WqkvT_*, 1: w_proj -> g_WprojT_*
__global__ void transpose_split(const float* __restrict__ W, int Kdim, int Ndim) {
    __nv_bfloat16* Thi = WHICH ? g_WprojT_hi : g_WqkvT_hi;
    __nv_bfloat16* Tlo = WHICH ? g_WprojT_lo : g_WqkvT_lo;
    __shared__ float tile[32][33];
    int x = blockIdx.x * 32 + threadIdx.x;
    int y0 = blockIdx.y * 32;
#pragma unroll
    for (int j = 0; j < 32; j += 8)
        tile[threadIdx.y + j][threadIdx.x] = W[(size_t)(y0 + threadIdx.y + j) * Ndim + x];
    __syncthreads();
    int xo = y0 + threadIdx.x;
    int yo0 = blockIdx.x * 32;
#pragma unroll
    for (int j = 0; j < 32; j += 8) {
        float v = tile[threadIdx.x][threadIdx.y + j];
        __nv_bfloat16 h = __float2bfloat16_rn(v);
        __nv_bfloat16 l = __float2bfloat16_rn(v - __bfloat162float(h));
        size_t o = (size_t)(yo0 + threadIdx.y + j) * Kdim + xo;
        Thi[o] = h; Tlo[o] = l;
    }
}

// ---------------------------------------------------------------------------
// HMMA GEMM, cp.async 3-stage ring, 2 CTAs/SM. Race-free ordering: the
// distance-2 prefetch into stage (c+2)%3 (== (c-1)%3) is issued AFTER the
// iteration barrier, so no lagging warp can still be reading that stage.
// wait_group 1 guarantees chunk c complete (its group was committed 2 iters
// earlier). 128x128 CTA tile, 8 warps, k-chunk 32; smem rows interleave
// [32 hi | 32 lo] bf16 (chunks 0-3 = hi, 4-7 = lo).
// acc += Ahi*Bhi + Ahi*Blo + Alo*Bhi. One __syncthreads per chunk.
// ---------------------------------------------------------------------------
#define GEMM_STG_BYTES 32768
#define GEMM_SMEM (3*GEMM_STG_BYTES)    // 98304 -> 2 CTAs/SM

__device__ __forceinline__ void gemm_prefetch(
    uint32_t sbase, const __nv_bfloat16* Ah, const __nv_bfloat16* Al,
    const __nv_bfloat16* Bh, const __nv_bfloat16* Bl,
    int m0, int n0, int k0, int tid) {
#pragma unroll
    for (int i = 0; i < 4; i++) {
        const int id = i * 256 + tid;          // 1024 chunk slots
        const int r = id >> 3, ch = id & 7;
        const uint32_t so = lda_sw(r, ch);
        const int kk = k0 + (ch & 3) * 8;      // hi: ch 0-3, lo: ch 4-7
        const size_t ga = (size_t)(m0 + r) * C_ + kk;
        const size_t gb = (size_t)(n0 + r) * C_ + kk;
        cpa16(sbase + so,         (ch < 4 ? Ah : Al) + ga);
        cpa16(sbase + 16384 + so, (ch < 4 ? Bh : Bl) + gb);
    }
}

template<int CFG>
__global__ __launch_bounds__(256, 2) void gemm_mma(const float* __restrict__ bias,
                                                   float* __restrict__ out) {
    extern __shared__ __align__(128) char gsm[];
    const __nv_bfloat16* Ah = CFG ? g_A2hi : g_Xhi;
    const __nv_bfloat16* Al = CFG ? g_A2lo : g_Xlo;
    const __nv_bfloat16* Bh = CFG ? g_WprojT_hi : g_WqkvT_hi;
    const __nv_bfloat16* Bl = CFG ? g_WprojT_lo : g_WqkvT_lo;

    const uint32_t sb = smem_to_u32(gsm);
    const int tid = threadIdx.x, lane = tid & 31, w = tid >> 5;
    const int wr = w >> 2, wc = w & 3;
    const int n0 = blockIdx.x * 128, m0 = blockIdx.y * 128;
    const int fr = lane & 15, fc = lane >> 4;

    float acc[4][4][4];
#pragma unroll
    for (int a = 0; a < 4; a++)
#pragma unroll
        for (int b = 0; b < 4; b++)
#pragma unroll
            for (int c = 0; c < 4; c++) acc[a][b][c] = 0.f;

    const int NCHUNK = C_ / 32;   // 32
    // Prologue: stages 0 and 1 in flight (groups for chunks 0 and 1).
    gemm_prefetch(sb, Ah, Al, Bh, Bl, m0, n0, 0, tid);
    CP_COMMIT();
    gemm_prefetch(sb + GEMM_STG_BYTES, Ah, Al, Bh, Bl, m0, n0, 32, tid);
    CP_COMMIT();

    int stg = 0;                  // stage index of chunk c32 (c32 % 3)
    for (int c32 = 0; c32 < NCHUNK; c32++) {
        // Before this wait, committed groups cover chunks 0..c32+1;
        // wait_group 1 => chunk c32's data is resident.
        CP_WAIT1();
        __syncthreads();          // no warp still reads stage (c32-1)%3 after this

        // Distance-2 prefetch into (c32+2)%3 == (c32-1)%3 — provably idle now.
        const int pst = (stg + 2 >= 3) ? stg - 1 : stg + 2;
        if (c32 + 2 < NCHUNK)
            gemm_prefetch(sb + pst * GEMM_STG_BYTES,
                          Ah, Al, Bh, Bl, m0, n0, (c32 + 2) * 32, tid);
        CP_COMMIT();              // unconditional: keeps group accounting uniform

        const uint32_t sA = sb + stg * GEMM_STG_BYTES;
        const uint32_t sB = sA + 16384;
#pragma unroll
        for (int ks = 0; ks < 2; ks++) {
            uint32_t a_h[4][4], a_l[4][4];
#pragma unroll
            for (int mt = 0; mt < 4; mt++) {
                const int ar = wr * 64 + mt * 16 + fr;
                ldsm4(a_h[mt], sA + lda_sw(ar, 2 * ks + fc));
                ldsm4(a_l[mt], sA + lda_sw(ar, 4 + 2 * ks + fc));
            }
#pragma unroll
            for (int nt2 = 0; nt2 < 2; nt2++) {
                uint32_t b_h[4], b_l[4];
                const int br = wc * 32 + nt2 * 16 + fr;
                ldsm4(b_h, sB + lda_sw(br, 2 * ks + fc));
                ldsm4(b_l, sB + lda_sw(br, 4 + 2 * ks + fc));
#pragma unroll
                for (int mt = 0; mt < 4; mt++) {
                    mma16816(acc[mt][nt2 * 2],     a_h[mt], b_h[0], b_h[2]);
                    mma16816(acc[mt][nt2 * 2 + 1], a_h[mt], b_h[1], b_h[3]);
                    mma16816(acc[mt][nt2 * 2],     a_h[mt], b_l[0], b_l[2]);
                    mma16816(acc[mt][nt2 * 2 + 1], a_h[mt], b_l[1], b_l[3]);
                    mma16816(acc[mt][nt2 * 2],     a_l[mt], b_h[0], b_h[2]);
                    mma16816(acc[mt][nt2 * 2 + 1], a_l[mt], b_h[1], b_h[3]);
                }
            }
        }
        stg = (stg + 1 >= 3) ? 0 : stg + 1;
    }

    // Epilogue
    const int grp = lane >> 2, qc = (lane & 3) * 2;
    const int which = n0 >> 10;      // CFG 0: 0=Q, 1=K, 2=V
#pragma unroll
    for (int mt = 0; mt < 4; mt++) {
        const int m1 = m0 + wr * 64 + mt * 16 + grp;
        const int m2 = m1 + 8;
        const int b1 = m1 >> 11, t1 = m1 & (T_ - 1);
        const int b2 = m2 >> 11, t2 = m2 & (T_ - 1);
#pragma unroll
        for (int nt = 0; nt < 4; nt++) {
            const int n = n0 + wc * 32 + nt * 8 + qc;
            const float bs0 = bias[n], bs1 = bias[n + 1];
            float v0 = acc[mt][nt][0] + bs0, v1 = acc[mt][nt][1] + bs1;
            float v2 = acc[mt][nt][2] + bs0, v3 = acc[mt][nt][3] + bs1;
            if (CFG == 1) {
                *(float2*)(out + (size_t)m1 * C_ + n) = make_float2(v0, v1);
                *(float2*)(out + (size_t)m2 * C_ + n) = make_float2(v2, v3);
            } else {
                const int ci = n & (C_ - 1);
                const int h = ci >> 6, d = ci & 63;
                if (which == 0) { v0 *= 0.125f; v1 *= 0.125f; v2 *= 0.125f; v3 *= 0.125f; }
                if (which < 2) {
                    __nv_bfloat16* Dh = which ? g_Khi : g_Qhi;
                    __nv_bfloat16* Dl = which ? g_Klo : g_Qlo;
                    store_hl2(Dh, Dl, (((size_t)(b1 * H_ + h)) * T_ + t1) * D_ + d, v0, v1);
                    store_hl2(Dh, Dl, (((size_t)(b2 * H_ + h)) * T_ + t2) * D_ + d, v2, v3);
                } else {
                    const size_t oA = (((size_t)(b1 * H_ + h)) * D_ + d) * T_ + t1;
                    const size_t oB = (((size_t)(b2 * H_ + h)) * D_ + d) * T_ + t2;
                    __nv_bfloat16 h0 = __float2bfloat16_rn(v0);
                    __nv_bfloat16 h1 = __float2bfloat16_rn(v1);
                    __nv_bfloat16 h2 = __float2bfloat16_rn(v2);
                    __nv_bfloat16 h3 = __float2bfloat16_rn(v3);
                    g_Vthi[oA] = h0;      g_Vtlo[oA] = __float2bfloat16_rn(v0 - __bfloat162float(h0));
                    g_Vthi[oA + T_] = h1; g_Vtlo[oA + T_] = __float2bfloat16_rn(v1 - __bfloat162float(h1));
                    g_Vthi[oB] = h2;      g_Vtlo[oB] = __float2bfloat16_rn(v2 - __bfloat162float(h2));
                    g_Vthi[oB + T_] = h3; g_Vtlo[oB + T_] = __float2bfloat16_rn(v3 - __bfloat162float(h3));
                }
            }
        }
    }
}

// ---------------------------------------------------------------------------
// HMMA flash attention, causal, cp.async 3-stage K/V ring with the same
// race-free ordering. Br=Bc=64, D=64, 4 warps, 2 CTAs/SM. Heavy q-tiles
// first. One __syncthreads per kv tile.
// ---------------------------------------------------------------------------
#define FL_Q_BYTES 16384                 // Qhi, Qlo [64][64]bf16
#define FL_STG_BYTES 32768               // Khi,Klo,Vthi,Vtlo per stage
#define FL_SMEM (FL_Q_BYTES + 3*FL_STG_BYTES)   // 114688

__device__ __forceinline__ void fl_prefetch(uint32_t sbase, size_t bhk,
                                            size_t bhv, int kv0, int tid) {
#pragma unroll
    for (int i = 0; i < 4; i++) {
        const int id = i * 128 + tid;
        const int r = id >> 3, ch = id & 7;
        const uint32_t so = lda_sw(r, ch);
        const size_t gk = bhk + (size_t)(kv0 + r) * D_ + ch * 8;
        const size_t gv = bhv + (size_t)r * T_ + kv0 + ch * 8;
        cpa16(sbase + so,         g_Khi + gk);
        cpa16(sbase + 8192 + so,  g_Klo + gk);
        cpa16(sbase + 16384 + so, g_Vthi + gv);
        cpa16(sbase + 24576 + so, g_Vtlo + gv);
    }
}

__global__ __launch_bounds__(128) void flash_mma() {
    extern __shared__ __align__(128) char fsm[];
    const uint32_t sb = smem_to_u32(fsm);
    const uint32_t sQh = sb, sQl = sb + 8192;
    const int tid = threadIdx.x, lane = tid & 31, w = tid >> 5;
    const int bh = blockIdx.y, b = bh >> 4, h = bh & 15;
    const int qtile = gridDim.x - 1 - blockIdx.x;   // heavy tiles first
    const int qt0 = qtile * 64;
    const int fr = lane & 15, fc = lane >> 4;
    const int grp = lane >> 2, qc = (lane & 3) * 2;
    const int ntiles = qtile + 1;

    const size_t bhk = (size_t)bh * T_ * D_;
    const size_t bhv = (size_t)bh * D_ * T_;

    // Prologue: stages 0 and 1 in flight.
    fl_prefetch(sb + FL_Q_BYTES, bhk, bhv, 0, tid);
    CP_COMMIT();
    if (1 < ntiles)
        fl_prefetch(sb + FL_Q_BYTES + FL_STG_BYTES, bhk, bhv, 64, tid);
    CP_COMMIT();

    // Load Q (plain loads)
#pragma unroll
    for (int i = 0; i < 4; i++) {
        const int id = i * 128 + tid;
        const int r = id >> 3, ch = id & 7;
        const uint32_t so = lda_sw(r, ch);
        const size_t g = bhk + (size_t)(qt0 + r) * D_ + ch * 8;
        *(uint4*)(fsm + so)        = *(const uint4*)(g_Qhi + g);
        *(uint4*)(fsm + 8192 + so) = *(const uint4*)(g_Qlo + g);
    }
    __syncthreads();

    uint32_t qh[4][4], ql[4][4];
#pragma unroll
    for (int ks = 0; ks < 4; ks++) {
        const uint32_t off = lda_sw(w * 16 + fr, 2 * ks + fc);
        ldsm4(qh[ks], sQh + off);
        ldsm4(ql[ks], sQl + off);
    }

    float o[8][4];
#pragma unroll
    for (int d = 0; d < 8; d++)
#pragma unroll
        for (int r = 0; r < 4; r++) o[d][r] = 0.f;
    float mA = -1e30f, mB = -1e30f, lA = 0.f, lB = 0.f;

    const int rowA = qt0 + w * 16 + grp;
    const int rowB = rowA + 8;

    int stg = 0;
    for (int it = 0; it < ntiles; it++) {
        CP_WAIT1();               // tile it resident (committed 2 iters ago)
        __syncthreads();          // stage (it-1)%3 no longer being read

        const int pst = (stg + 2 >= 3) ? stg - 1 : stg + 2;
        if (it + 2 < ntiles)
            fl_prefetch(sb + FL_Q_BYTES + pst * FL_STG_BYTES,
                        bhk, bhv, (it + 2) * 64, tid);
        CP_COMMIT();

        const uint32_t sKh = sb + FL_Q_BYTES + stg * FL_STG_BYTES;
        const uint32_t sKl = sKh + 8192, sVh = sKh + 16384, sVl = sKh + 24576;
        const int kv0 = it * 64;

        float s[8][4];
#pragma unroll
        for (int nt = 0; nt < 8; nt++)
#pragma unroll
            for (int r = 0; r < 4; r++) s[nt][r] = 0.f;

#pragma unroll
        for (int ks = 0; ks < 4; ks++) {
#pragma unroll
            for (int nt2 = 0; nt2 < 4; nt2++) {
                uint32_t bhr[4], blr[4];
                const uint32_t off = lda_sw(nt2 * 16 + fr, 2 * ks + fc);
                ldsm4(bhr, sKh + off);
                ldsm4(blr, sKl + off);
                mma16816(s[nt2 * 2],     qh[ks], bhr[0], bhr[2]);
                mma16816(s[nt2 * 2 + 1], qh[ks], bhr[1], bhr[3]);
                mma16816(s[nt2 * 2],     qh[ks], blr[0], blr[2]);
                mma16816(s[nt2 * 2 + 1], qh[ks], blr[1], blr[3]);
                mma16816(s[nt2 * 2],     ql[ks], bhr[0], bhr[2]);
                mma16816(s[nt2 * 2 + 1], ql[ks], bhr[1], bhr[3]);
            }
        }

        if (kv0 == qt0) {
#pragma unroll
            for (int nt = 0; nt < 8; nt++) {
                const int cb = kv0 + nt * 8 + qc;
                if (cb > rowA)     s[nt][0] = -1e30f;
                if (cb + 1 > rowA) s[nt][1] = -1e30f;
                if (cb > rowB)     s[nt][2] = -1e30f;
                if (cb + 1 > rowB) s[nt][3] = -1e30f;
            }
        }

        float mxA = -1e30f, mxB = -1e30f;
#pragma unroll
        for (int nt = 0; nt < 8; nt++) {
            mxA = fmaxf(mxA, fmaxf(s[nt][0], s[nt][1]));
            mxB = fmaxf(mxB, fmaxf(s[nt][2], s[nt][3]));
        }
        mxA = fmaxf(mxA, __shfl_xor_sync(0xffffffffu, mxA, 1));
        mxA = fmaxf(mxA, __shfl_xor_sync(0xffffffffu, mxA, 2));
        mxB = fmaxf(mxB, __shfl_xor_sync(0xffffffffu, mxB, 1));
        mxB = fmaxf(mxB, __shfl_xor_sync(0xffffffffu, mxB, 2));
        const float nmA = fmaxf(mA, mxA), nmB = fmaxf(mB, mxB);
        const float aA = __expf(mA - nmA), aB = __expf(mB - nmB);

        float p[8][4];
        float sumA = 0.f, sumB = 0.f;
#pragma unroll
        for (int nt = 0; nt < 8; nt++) {
            p[nt][0] = __expf(s[nt][0] - nmA);
            p[nt][1] = __expf(s[nt][1] - nmA);
            p[nt][2] = __expf(s[nt][2] - nmB);
            p[nt][3] = __expf(s[nt][3] - nmB);
            sumA += p[nt][0] + p[nt][1];
            sumB += p[nt][2] + p[nt][3];
        }
        sumA += __shfl_xor_sync(0xffffffffu, sumA, 1);
        sumA += __shfl_xor_sync(0xffffffffu, sumA, 2);
        sumB += __shfl_xor_sync(0xffffffffu, sumB, 1);
        sumB += __shfl_xor_sync(0xffffffffu, sumB, 2);
        lA = lA * aA + sumA;
        lB = lB * aB + sumB;
        mA = nmA; mB = nmB;
#pragma unroll
        for (int d = 0; d < 8; d++) {
            o[d][0] *= aA; o[d][1] *= aA;
            o[d][2] *= aB; o[d][3] *= aB;
        }

#pragma unroll
        for (int ks = 0; ks < 4; ks++) {
            float f0 = p[2 * ks][0], f1 = p[2 * ks][1];
            float f2 = p[2 * ks][2], f3 = p[2 * ks][3];
            float f4 = p[2 * ks + 1][0], f5 = p[2 * ks + 1][1];
            float f6 = p[2 * ks + 1][2], f7 = p[2 * ks + 1][3];
            float h0 = __bfloat162float(__float2bfloat16_rn(f0));
            float h1 = __bfloat162float(__float2bfloat16_rn(f1));
            float h2 = __bfloat162float(__float2bfloat16_rn(f2));
            float h3 = __bfloat162float(__float2bfloat16_rn(f3));
            float h4 = __bfloat162float(__float2bfloat16_rn(f4));
            float h5 = __bfloat162float(__float2bfloat16_rn(f5));
            float h6 = __bfloat162float(__float2bfloat16_rn(f6));
            float h7 = __bfloat162float(__float2bfloat16_rn(f7));
            uint32_t pa_h[4], pa_l[4];
            pa_h[0] = pack_bf16(h0, h1); pa_h[1] = pack_bf16(h2, h3);
            pa_h[2] = pack_bf16(h4, h5); pa_h[3] = pack_bf16(h6, h7);
            pa_l[0] = pack_bf16(f0 - h0, f1 - h1);
            pa_l[1] = pack_bf16(f2 - h2, f3 - h3);
            pa_l[2] = pack_bf16(f4 - h4, f5 - h5);
            pa_l[3] = pack_bf16(f6 - h6, f7 - h7);
#pragma unroll
            for (int dt2 = 0; dt2 < 4; dt2++) {
                uint32_t vh4[4], vl4[4];
                const uint32_t off = lda_sw(dt2 * 16 + fr, 2 * ks + fc);
                ldsm4(vh4, sVh + off);
                ldsm4(vl4, sVl + off);
                mma16816(o[dt2 * 2],     pa_h, vh4[0], vh4[2]);
                mma16816(o[dt2 * 2 + 1], pa_h, vh4[1], vh4[3]);
                mma16816(o[dt2 * 2],     pa_h, vl4[0], vl4[2]);
                mma16816(o[dt2 * 2 + 1], pa_h, vl4[1], vl4[3]);
                mma16816(o[dt2 * 2],     pa_l, vh4[0], vh4[2]);
                mma16816(o[dt2 * 2 + 1], pa_l, vh4[1], vh4[3]);
            }
        }
        stg = (stg + 1 >= 3) ? 0 : stg + 1;
    }

    const float invA = 1.0f / lA, invB = 1.0f / lB;
    const size_t baseA = ((size_t)(b * T_ + rowA)) * C_ + h * D_;
    const size_t baseB = ((size_t)(b * T_ + rowB)) * C_ + h * D_;
#pragma unroll
    for (int dt = 0; dt < 8; dt++) {
        const int d = dt * 8 + qc;
        store_hl2(g_A2hi, g_A2lo, baseA + d, o[dt][0] * invA, o[dt][1] * invA);
        store_hl2(g_A2hi, g_A2lo, baseB + d, o[dt][2] * invB, o[dt][3] * invB);
    }
}

// ---------------------------------------------------------------------------
extern "C" void kernel_launch(void* const* d_in, const int* in_sizes, int n_in,
                              void* d_out, int out_size) {
    const float* x      = (const float*)d_in[0];
    const float* w_qkv  = (const float*)d_in[1];
    const float* b_qkv  = (const float*)d_in[2];
    const float* w_proj = (const float*)d_in[3];
    const float* b_proj = (const float*)d_in[4];
    float* out = (float*)d_out;

    cudaFuncSetAttribute(gemm_mma<0>, cudaFuncAttributeMaxDynamicSharedMemorySize, GEMM_SMEM);
    cudaFuncSetAttribute(gemm_mma<1>, cudaFuncAttributeMaxDynamicSharedMemorySize, GEMM_SMEM);
    cudaFuncSetAttribute(flash_mma,   cudaFuncAttributeMaxDynamicSharedMemorySize, FL_SMEM);

    // 0) input conversions
    conv_x<<<(M_ * C_ / 4) / 256, 256>>>(x);
    transpose_split<0><<<dim3(N3_ / 32, C_ / 32), dim3(32, 8)>>>(w_qkv, C_, N3_);
    transpose_split<1><<<dim3(C_ / 32, C_ / 32), dim3(32, 8)>>>(w_proj, C_, C_);

    // 1) QKV GEMM (race-free 3-stage HMMA, 2 CTA/SM) -> fused bf16 Q/K/Vt epilogue
    gemm_mma<0><<<dim3(N3_ / 128, M_ / 128), 256, GEMM_SMEM>>>(b_qkv, nullptr);

    // 2) Causal flash attention (race-free 3-stage HMMA) -> g_A2 hi/lo
    flash_mma<<<dim3(T_ / 64, BH_), 128, FL_SMEM>>>();

    // 3) Output projection (race-free 3-stage HMMA, 2 CTA/SM) -> fp32 out
    gemm_mma<1><<<dim3(C_ / 128, M_ / 128), 256, GEMM_SMEM>>>(b_proj, out);
}